// round 15
// baseline (speedup 1.0000x reference)
#include <cuda_runtime.h>
#include <cstdint>

#define BATCH 16
#define HH 56
#define WW 56
#define NPIX (HH * WW)
#define EPSV 1e-5f

// ---------------- scratch (device globals; no allocation) ----------------
__device__ uint32_t g_Abits[BATCH * 8 * HH * WW];    // stage1 input bits  [b][w][y][x]
__device__ uint32_t g_Sbits[BATCH * 16 * HH * WW];   // stage2 input bits  [b][w][y][x]
__device__ float    g_Out1f[BATCH * 128 * HH * WW];  // out1 channels 0..127
__device__ uint32_t g_W1b[72 * 256];                 // [k][oc]
__device__ uint32_t g_W2b[144 * 256];                // permuted for shuffle
__device__ int      g_NW1[9 * 256];
__device__ int      g_NW2[9 * 256];
__device__ float    g_alpha1[256], g_c1[256], g_alpha2[256], g_c2[256];

// ---------------- weight prep ----------------
__global__ void prep_w1(const float* __restrict__ w1, const float* __restrict__ gm,
                        const float* __restrict__ bt, const float* __restrict__ mn,
                        const float* __restrict__ vr) {
    int oc = blockIdx.x;
    int c  = threadIdx.x;
    int lane = c & 31, wi = c >> 5;
    __shared__ int nw[9];
    __shared__ float red[8];
    if (c < 9) nw[c] = 0;
    __syncthreads();
    float asum = 0.f;
#pragma unroll
    for (int r = 0; r < 3; r++)
#pragma unroll
        for (int dx = 0; dx < 3; dx++) {
            float v = w1[((oc * 256 + c) * 3 + r) * 3 + dx];
            asum += fabsf(v);
            unsigned word = __ballot_sync(0xffffffffu, v < 0.f);
            if (lane == 0) {
                int k = (wi * 3 + r) * 3 + dx;
                g_W1b[k * 256 + oc] = word;
                atomicAdd(&nw[r * 3 + dx], __popc(word));
            }
        }
    __syncthreads();
    if (c < 9) g_NW1[c * 256 + oc] = nw[c];
    for (int o = 16; o > 0; o >>= 1) asum += __shfl_xor_sync(0xffffffffu, asum, o);
    if (lane == 0) red[wi] = asum;
    __syncthreads();
    if (c == 0) {
        float s = 0.f;
#pragma unroll
        for (int i = 0; i < 8; i++) s += red[i];
        float scale = s / (256.f * 9.f);
        float inv = gm[oc] / sqrtf(vr[oc] + EPSV);
        g_alpha1[oc] = scale * inv;
        g_c1[oc] = bt[oc] - mn[oc] * inv;
    }
}

__global__ void prep_w2(const float* __restrict__ w2, const float* __restrict__ gm,
                        const float* __restrict__ bt, const float* __restrict__ mn,
                        const float* __restrict__ vr) {
    int oc = blockIdx.x;
    int c  = threadIdx.x;
    int lane = c & 31;
    __shared__ int nw[9];
    __shared__ float red[8];
    if (c < 9) nw[c] = 0;
    __syncthreads();
    float asum = 0.f;
    for (int it = 0; it < 2; it++) {
        int j  = it * 256 + c;
        int ic = (j < 256) ? (2 * j) : (2 * (j - 256) + 1);
        int wi = j >> 5;
#pragma unroll
        for (int r = 0; r < 3; r++)
#pragma unroll
            for (int dx = 0; dx < 3; dx++) {
                float v = w2[((oc * 512 + ic) * 3 + r) * 3 + dx];
                asum += fabsf(v);
                unsigned word = __ballot_sync(0xffffffffu, v < 0.f);
                if (lane == 0) {
                    int k = (wi * 3 + r) * 3 + dx;
                    g_W2b[k * 256 + oc] = word;
                    atomicAdd(&nw[r * 3 + dx], __popc(word));
                }
            }
    }
    __syncthreads();
    if (c < 9) g_NW2[c * 256 + oc] = nw[c];
    for (int o = 16; o > 0; o >>= 1) asum += __shfl_xor_sync(0xffffffffu, asum, o);
    if (lane == 0) red[c >> 5] = asum;
    __syncthreads();
    if (c == 0) {
        float s = 0.f;
#pragma unroll
        for (int i = 0; i < 8; i++) s += red[i];
        float scale = s / (512.f * 9.f);
        float inv = gm[oc] / sqrtf(vr[oc] + EPSV);
        g_alpha2[oc] = scale * inv;
        g_c2[oc] = bt[oc] - mn[oc] * inv;
    }
}

// ---------------- input packing (word-parallel) ----------------
__global__ __launch_bounds__(256) void pack_input(const float* __restrict__ x,
                                                  const float* __restrict__ mb) {
    int n = blockIdx.x * blockDim.x + threadIdx.x;
    if (n >= BATCH * 16 * NPIX) return;
    int xw = n % NPIX;
    int t  = n / NPIX;
    int wi = t & 15;
    int b  = t >> 4;
    if (wi < 8) {
        const float* xp = x + ((size_t)b * 512 + wi * 32) * NPIX + xw;
        uint32_t word = 0;
#pragma unroll
        for (int k = 0; k < 32; k++) {
            float v = __ldg(&xp[(size_t)k * NPIX]);
            word |= (v < 0.f ? 1u : 0u) << k;
        }
        g_Abits[(b * 8 + wi) * NPIX + xw] = word;
    } else {
        int w2 = wi - 8;
        const float* xp = x + ((size_t)b * 512 + 256 + w2 * 32) * NPIX + xw;
        uint32_t word = 0;
#pragma unroll
        for (int k = 0; k < 32; k++) {
            float v = __ldg(&xp[(size_t)k * NPIX]) + __ldg(&mb[w2 * 32 + k]);
            word |= (v < 0.f ? 1u : 0u) << k;
        }
        g_Sbits[(b * 16 + 8 + w2) * NPIX + xw] = word;
    }
}

__device__ __forceinline__ uint32_t maj3(uint32_t a, uint32_t b, uint32_t c) {
    return (a & b) | (b & c) | (a & c);   // single LOP3, LUT 0xE8
}
__device__ __forceinline__ uint32_t xor3(uint32_t a, uint32_t b, uint32_t c) {
    return a ^ b ^ c;                      // single LOP3, LUT 0x96
}

// ---------------- binarized conv (XOR + row CSA, fma-pipe accumulates) ----
// Block: 256 threads; tile = 56 px (one row) x 64 oc. Thread: 7 px x 2 oc.
// CSA: popc(x0)+popc(x1)+popc(x2) = popc(xor3)+2*popc(maj3).
// Packed acc: lo16 = 6 * sum popc(xor3)  (IMAD x6 -> fma pipe; /6 in epilogue)
//             hi16 =     sum popc(maj3)  (IMAD x65536 -> fma pipe)
// Both accumulates now on fma; alu pipe keeps only XOR/LOP3/POPC.
// HALVES=2 (stage2): only half of Ws resident; reloaded once.
template <int WORDS, int STAGE, int MINB, int HALVES>
__global__ __launch_bounds__(256, MINB) void binconv(const float* __restrict__ x,
                                                     const float* __restrict__ mb,
                                                     float* __restrict__ out) {
    constexpr int CTOT = WORDS * 32;
    constexpr int WPH  = WORDS / HALVES;         // words per half
    constexpr int KRES = WPH * 9;                // k-entries resident in Ws
    extern __shared__ uint32_t smem[];
    uint32_t* Ws = smem;                          // [KRES][64]  (reused post-mainloop)
    uint32_t* As = smem + KRES * 64;              // [WORDS*3][58]
    float*    Rs = (float*)(As + WORDS * 3 * 58); // stage1: [64][57] residual -> Vs
    float*    Vs = (STAGE == 1) ? Rs : (float*)Ws;
    uint32_t* stg = Ws;                           // stage1 sign-bit staging

    const uint32_t* Gb = (STAGE == 1) ? g_Abits : g_Sbits;
    const uint32_t* Wg = (STAGE == 1) ? g_W1b : g_W2b;

    int ocq = blockIdx.x;        // oc quarter (64 oc)
    int y = blockIdx.y;
    int b = blockIdx.z;
    int tid = threadIdx.x;
    int og = tid & 31;           // lane: oc pair index
    int g  = tid >> 5;           // warp: pixel group (7 px)

    uint32_t acc[7][2];
#pragma unroll
    for (int p = 0; p < 7; p++) { acc[p][0] = 0; acc[p][1] = 0; }

#pragma unroll 1
    for (int half = 0; half < HALVES; half++) {
        if (HALVES > 1 && half > 0) __syncthreads();   // prior-half Ws reads done
        // ---- cooperative loads ----
        for (int idx = tid; idx < KRES * 64; idx += 256) {
            int k = idx >> 6, o = idx & 63;
            Ws[idx] = Wg[(half * KRES + k) * 256 + ocq * 64 + o];
        }
        if (half == 0) {
            for (int idx = tid; idx < WORDS * 3 * 58; idx += 256) {
                int c = idx % 58;
                int wr = idx / 58;
                int r = wr % 3, w = wr / 3;
                int yy = y + r - 1;
                int xx = c - 1;
                uint32_t v = 0;
                if ((unsigned)yy < HH && (unsigned)xx < WW)
                    v = Gb[((b * WORDS + w) * HH + yy) * WW + xx];
                As[wr * 58 + c] = v;
            }
            if (STAGE == 1) {
                for (int idx = tid; idx < 64 * WW; idx += 256) {
                    int oc_l = idx / WW, px = idx % WW;
                    Rs[oc_l * 57 + px] =
                        __ldg(&x[(((size_t)b * 512 + ocq * 64 + oc_l) * HH + y) * WW + px]);
                }
            }
        }
        __syncthreads();

        // ---- main loop (this half) ----
#pragma unroll 4
        for (int wl = 0; wl < WPH; wl++) {
            int w = half * WPH + wl;               // global word index (As)
#pragma unroll
            for (int r = 0; r < 3; r++) {
                const uint32_t* arow = &As[(w * 3 + r) * 58 + 7 * g];
                uint32_t a[9];
#pragma unroll
                for (int i = 0; i < 9; i++) a[i] = arow[i];
                int k0 = (wl * 3 + r) * 3;          // local k index (Ws)
                uint2 w0 = *reinterpret_cast<const uint2*>(&Ws[(k0 + 0) * 64 + og * 2]);
                uint2 w1 = *reinterpret_cast<const uint2*>(&Ws[(k0 + 1) * 64 + og * 2]);
                uint2 w2 = *reinterpret_cast<const uint2*>(&Ws[(k0 + 2) * 64 + og * 2]);
#pragma unroll
                for (int p = 0; p < 7; p++) {
                    {
                        uint32_t x0 = a[p] ^ w0.x, x1 = a[p + 1] ^ w1.x, x2 = a[p + 2] ^ w2.x;
                        uint32_t t = acc[p][0];
                        t = __popc(maj3(x0, x1, x2)) * 65536u + t;   // IMAD (fma pipe)
                        t = __popc(xor3(x0, x1, x2)) * 6u + t;       // IMAD (fma pipe; not LEA-able)
                        acc[p][0] = t;
                    }
                    {
                        uint32_t x0 = a[p] ^ w0.y, x1 = a[p + 1] ^ w1.y, x2 = a[p + 2] ^ w2.y;
                        uint32_t t = acc[p][1];
                        t = __popc(maj3(x0, x1, x2)) * 65536u + t;
                        t = __popc(xor3(x0, x1, x2)) * 6u + t;
                        acc[p][1] = t;
                    }
                }
            }
        }
    }
    __syncthreads();   // Ws reads done; region reusable

    // ---- epilogue ----
    int ocbase = ocq * 64 + og * 2;
    const float* Ag = (STAGE == 1) ? g_alpha1 : g_alpha2;
    const float* Cg = (STAGE == 1) ? g_c1 : g_c2;
    const int* NWg = (STAGE == 1) ? g_NW1 : g_NW2;
    float alpha[2], cc[2];
#pragma unroll
    for (int j = 0; j < 2; j++) { alpha[j] = __ldg(&Ag[ocbase + j]); cc[j] = __ldg(&Cg[ocbase + j]); }
    bool ybord = (y == 0) || (y == HH - 1);

#pragma unroll
    for (int p = 0; p < 7; p++) {
        int xx = 7 * g + p;
        bool bord = ybord || (xx == 0) || (xx == WW - 1);
        int nv = 9;
        int corr[2] = {0, 0};
        if (bord) {
#pragma unroll
            for (int t = 0; t < 9; t++) {
                int dy = t / 3 - 1, dx = t % 3 - 1;
                if ((unsigned)(y + dy) >= HH || (unsigned)(xx + dx) >= WW) {
                    nv--;
                    corr[0] += __ldg(&NWg[t * 256 + ocbase]);
                    corr[1] += __ldg(&NWg[t * 256 + ocbase + 1]);
                }
            }
        }
        if (STAGE == 1) {
            uint32_t sb = 0;
#pragma unroll
            for (int j = 0; j < 2; j++) {
                uint32_t av = acc[p][j];
                int ones = (int)((av & 0xFFFFu) / 6u) + 2 * (int)(av >> 16);
                int dot = CTOT * nv - 2 * ones + 2 * corr[j];
                float val = (float)dot * alpha[j] + cc[j];
                val += Rs[(og * 2 + j) * 57 + xx];
                val = fminf(fmaxf(val, -1.f), 1.f);
                Vs[(og * 2 + j) * 57 + xx] = val;
                sb |= (val < 0.f ? 1u : 0u) << j;
            }
            stg[xx * 32 + og] = sb;
        } else {
#pragma unroll
            for (int j = 0; j < 2; j++) {
                uint32_t av = acc[p][j];
                int ones = (int)((av & 0xFFFFu) / 6u) + 2 * (int)(av >> 16);
                int dot = CTOT * nv - 2 * ones + 2 * corr[j];
                Vs[(og * 2 + j) * 57 + xx] = (float)dot * alpha[j] + cc[j];
            }
        }
    }
    __syncthreads();

    // ---- coalesced writeout ----
    if (STAGE == 1) {
        if (ocq < 2) {
            for (int idx = tid; idx < 64 * WW; idx += 256) {
                int oc_l = idx / WW, px = idx % WW;
                g_Out1f[(((size_t)b * 128 + ocq * 64 + oc_l) * HH + y) * WW + px] =
                    Vs[oc_l * 57 + px];
            }
        }
        if (tid < 2 * WW) {
            int px = tid >> 1, wsel = tid & 1;
            uint32_t word = 0;
#pragma unroll
            for (int q = 0; q < 16; q++) {
                uint32_t v = stg[px * 32 + wsel * 16 + q];
                word |= (v & 1u) << (2 * q);
                word |= ((v >> 1) & 1u) << (2 * q + 1);
            }
            g_Sbits[((b * 16 + (ocq * 2 + wsel)) * HH + y) * WW + px] = word;
        }
    } else {
        for (int idx = tid; idx < 64 * WW; idx += 256) {
            int oc_l = idx / WW, px = idx % WW;
            int oc = ocq * 64 + oc_l;
            float v = Vs[oc_l * 57 + px];
            float res;
            if ((oc & 1) == 0)
                res = __ldg(&g_Out1f[(((size_t)b * 128 + (oc >> 1)) * HH + y) * WW + px]);
            else
                res = __ldg(&x[(((size_t)b * 512 + 256 + (oc >> 1)) * HH + y) * WW + px]) +
                      __ldg(&mb[oc >> 1]);
            v = fminf(fmaxf(v + res, -1.f), 1.f);
            out[(((size_t)b * 256 + oc) * HH + y) * WW + px] = v;
        }
    }
}

// ---------------- launch ----------------
extern "C" void kernel_launch(void* const* d_in, const int* in_sizes, int n_in,
                              void* d_out, int out_size) {
    const float* x      = (const float*)d_in[0];
    const float* w1     = (const float*)d_in[1];
    const float* w2     = (const float*)d_in[2];
    const float* gamma1 = (const float*)d_in[3];
    const float* beta1  = (const float*)d_in[4];
    const float* mean1  = (const float*)d_in[5];
    const float* var1   = (const float*)d_in[6];
    const float* gamma2 = (const float*)d_in[7];
    const float* beta2  = (const float*)d_in[8];
    const float* mean2  = (const float*)d_in[9];
    const float* var2   = (const float*)d_in[10];
    const float* mb     = (const float*)d_in[11];
    float* out = (float*)d_out;

    const int smem1 = (72 * 64 + 8 * 3 * 58 + 64 * 57) * 4;
    const int smem2 = (72 * 64 + 16 * 3 * 58) * 4;
    cudaFuncSetAttribute(binconv<8, 1, 5, 1>,  cudaFuncAttributeMaxDynamicSharedMemorySize, smem1);
    cudaFuncSetAttribute(binconv<16, 2, 5, 2>, cudaFuncAttributeMaxDynamicSharedMemorySize, smem2);

    prep_w1<<<256, 256>>>(w1, gamma1, beta1, mean1, var1);
    prep_w2<<<256, 256>>>(w2, gamma2, beta2, mean2, var2);
    pack_input<<<(BATCH * 16 * NPIX + 255) / 256, 256>>>(x, mb);

    dim3 grid(4, HH, BATCH);
    binconv<8, 1, 5, 1><<<grid, 256, smem1>>>(x, mb, out);
    binconv<16, 2, 5, 2><<<grid, 256, smem2>>>(x, mb, out);
}

// round 16
// speedup vs baseline: 1.0082x; 1.0082x over previous
#include <cuda_runtime.h>
#include <cstdint>

#define BATCH 16
#define HH 56
#define WW 56
#define NPIX (HH * WW)
#define EPSV 1e-5f

// ---------------- scratch (device globals; no allocation) ----------------
__device__ uint32_t g_Abits[BATCH * 8 * HH * WW];    // stage1 input bits  [b][w][y][x]
__device__ uint32_t g_Sbits[BATCH * 16 * HH * WW];   // stage2 input bits  [b][w][y][x]
__device__ float    g_Out1f[BATCH * 128 * HH * WW];  // out1 channels 0..127
__device__ uint32_t g_W1b[72 * 256];                 // [k][oc]
__device__ uint32_t g_W2b[144 * 256];                // permuted for shuffle
__device__ int      g_NW1[9 * 256];
__device__ int      g_NW2[9 * 256];
__device__ float    g_alpha1[256], g_c1[256], g_alpha2[256], g_c2[256];

// ---------------- weight prep ----------------
__global__ void prep_w1(const float* __restrict__ w1, const float* __restrict__ gm,
                        const float* __restrict__ bt, const float* __restrict__ mn,
                        const float* __restrict__ vr) {
    int oc = blockIdx.x;
    int c  = threadIdx.x;
    int lane = c & 31, wi = c >> 5;
    __shared__ int nw[9];
    __shared__ float red[8];
    if (c < 9) nw[c] = 0;
    __syncthreads();
    float asum = 0.f;
#pragma unroll
    for (int r = 0; r < 3; r++)
#pragma unroll
        for (int dx = 0; dx < 3; dx++) {
            float v = w1[((oc * 256 + c) * 3 + r) * 3 + dx];
            asum += fabsf(v);
            unsigned word = __ballot_sync(0xffffffffu, v < 0.f);
            if (lane == 0) {
                int k = (wi * 3 + r) * 3 + dx;
                g_W1b[k * 256 + oc] = word;
                atomicAdd(&nw[r * 3 + dx], __popc(word));
            }
        }
    __syncthreads();
    if (c < 9) g_NW1[c * 256 + oc] = nw[c];
    for (int o = 16; o > 0; o >>= 1) asum += __shfl_xor_sync(0xffffffffu, asum, o);
    if (lane == 0) red[wi] = asum;
    __syncthreads();
    if (c == 0) {
        float s = 0.f;
#pragma unroll
        for (int i = 0; i < 8; i++) s += red[i];
        float scale = s / (256.f * 9.f);
        float inv = gm[oc] / sqrtf(vr[oc] + EPSV);
        g_alpha1[oc] = scale * inv;
        g_c1[oc] = bt[oc] - mn[oc] * inv;
    }
}

__global__ void prep_w2(const float* __restrict__ w2, const float* __restrict__ gm,
                        const float* __restrict__ bt, const float* __restrict__ mn,
                        const float* __restrict__ vr) {
    int oc = blockIdx.x;
    int c  = threadIdx.x;
    int lane = c & 31;
    __shared__ int nw[9];
    __shared__ float red[8];
    if (c < 9) nw[c] = 0;
    __syncthreads();
    float asum = 0.f;
    for (int it = 0; it < 2; it++) {
        int j  = it * 256 + c;
        int ic = (j < 256) ? (2 * j) : (2 * (j - 256) + 1);
        int wi = j >> 5;
#pragma unroll
        for (int r = 0; r < 3; r++)
#pragma unroll
            for (int dx = 0; dx < 3; dx++) {
                float v = w2[((oc * 512 + ic) * 3 + r) * 3 + dx];
                asum += fabsf(v);
                unsigned word = __ballot_sync(0xffffffffu, v < 0.f);
                if (lane == 0) {
                    int k = (wi * 3 + r) * 3 + dx;
                    g_W2b[k * 256 + oc] = word;
                    atomicAdd(&nw[r * 3 + dx], __popc(word));
                }
            }
    }
    __syncthreads();
    if (c < 9) g_NW2[c * 256 + oc] = nw[c];
    for (int o = 16; o > 0; o >>= 1) asum += __shfl_xor_sync(0xffffffffu, asum, o);
    if (lane == 0) red[c >> 5] = asum;
    __syncthreads();
    if (c == 0) {
        float s = 0.f;
#pragma unroll
        for (int i = 0; i < 8; i++) s += red[i];
        float scale = s / (512.f * 9.f);
        float inv = gm[oc] / sqrtf(vr[oc] + EPSV);
        g_alpha2[oc] = scale * inv;
        g_c2[oc] = bt[oc] - mn[oc] * inv;
    }
}

// ---------------- input packing (word-parallel) ----------------
__global__ __launch_bounds__(256) void pack_input(const float* __restrict__ x,
                                                  const float* __restrict__ mb) {
    int n = blockIdx.x * blockDim.x + threadIdx.x;
    if (n >= BATCH * 16 * NPIX) return;
    int xw = n % NPIX;
    int t  = n / NPIX;
    int wi = t & 15;
    int b  = t >> 4;
    if (wi < 8) {
        const float* xp = x + ((size_t)b * 512 + wi * 32) * NPIX + xw;
        uint32_t word = 0;
#pragma unroll
        for (int k = 0; k < 32; k++) {
            float v = __ldg(&xp[(size_t)k * NPIX]);
            word |= (v < 0.f ? 1u : 0u) << k;
        }
        g_Abits[(b * 8 + wi) * NPIX + xw] = word;
    } else {
        int w2 = wi - 8;
        const float* xp = x + ((size_t)b * 512 + 256 + w2 * 32) * NPIX + xw;
        uint32_t word = 0;
#pragma unroll
        for (int k = 0; k < 32; k++) {
            float v = __ldg(&xp[(size_t)k * NPIX]) + __ldg(&mb[w2 * 32 + k]);
            word |= (v < 0.f ? 1u : 0u) << k;
        }
        g_Sbits[(b * 16 + 8 + w2) * NPIX + xw] = word;
    }
}

__device__ __forceinline__ uint32_t maj3(uint32_t a, uint32_t b, uint32_t c) {
    return (a & b) | (b & c) | (a & c);   // single LOP3, LUT 0xE8
}
__device__ __forceinline__ uint32_t xor3(uint32_t a, uint32_t b, uint32_t c) {
    return a ^ b ^ c;                      // single LOP3, LUT 0x96
}

// ---------------- binarized conv (XOR + row CSA, packed accs) -------------
// Block: 256 threads; tile = 56 px (one row) x 64 oc. Thread: 7 px x 2 oc.
// CSA: popc(x0)+popc(x1)+popc(x2) = popc(xor3)+2*popc(maj3).
// Packed acc: lo16 = sum popc(xor3), hi16 = sum popc(maj3).
// HALVES=1 both stages (no Ws reload / no mid-loop sync; measured best).
template <int WORDS, int STAGE, int MINB, int HALVES>
__global__ __launch_bounds__(256, MINB) void binconv(const float* __restrict__ x,
                                                     const float* __restrict__ mb,
                                                     float* __restrict__ out) {
    constexpr int CTOT = WORDS * 32;
    constexpr int WPH  = WORDS / HALVES;         // words per half
    constexpr int KRES = WPH * 9;                // k-entries resident in Ws
    extern __shared__ uint32_t smem[];
    uint32_t* Ws = smem;                          // [KRES][64]  (reused post-mainloop)
    uint32_t* As = smem + KRES * 64;              // [WORDS*3][58]
    float*    Rs = (float*)(As + WORDS * 3 * 58); // stage1: [64][57] residual -> Vs
    float*    Vs = (STAGE == 1) ? Rs : (float*)Ws;
    uint32_t* stg = Ws;                           // stage1 sign-bit staging

    const uint32_t* Gb = (STAGE == 1) ? g_Abits : g_Sbits;
    const uint32_t* Wg = (STAGE == 1) ? g_W1b : g_W2b;

    int ocq = blockIdx.x;        // oc quarter (64 oc)
    int y = blockIdx.y;
    int b = blockIdx.z;
    int tid = threadIdx.x;
    int og = tid & 31;           // lane: oc pair index
    int g  = tid >> 5;           // warp: pixel group (7 px)

    uint32_t acc[7][2];
#pragma unroll
    for (int p = 0; p < 7; p++) { acc[p][0] = 0; acc[p][1] = 0; }

#pragma unroll 1
    for (int half = 0; half < HALVES; half++) {
        if (HALVES > 1 && half > 0) __syncthreads();   // prior-half Ws reads done
        // ---- cooperative loads ----
        for (int idx = tid; idx < KRES * 64; idx += 256) {
            int k = idx >> 6, o = idx & 63;
            Ws[idx] = Wg[(half * KRES + k) * 256 + ocq * 64 + o];
        }
        if (half == 0) {
            for (int idx = tid; idx < WORDS * 3 * 58; idx += 256) {
                int c = idx % 58;
                int wr = idx / 58;
                int r = wr % 3, w = wr / 3;
                int yy = y + r - 1;
                int xx = c - 1;
                uint32_t v = 0;
                if ((unsigned)yy < HH && (unsigned)xx < WW)
                    v = Gb[((b * WORDS + w) * HH + yy) * WW + xx];
                As[wr * 58 + c] = v;
            }
            if (STAGE == 1) {
                for (int idx = tid; idx < 64 * WW; idx += 256) {
                    int oc_l = idx / WW, px = idx % WW;
                    Rs[oc_l * 57 + px] =
                        __ldg(&x[(((size_t)b * 512 + ocq * 64 + oc_l) * HH + y) * WW + px]);
                }
            }
        }
        __syncthreads();

        // ---- main loop (unroll 4 widens the LDS scheduling window) ----
#pragma unroll 4
        for (int wl = 0; wl < WPH; wl++) {
            int w = half * WPH + wl;               // global word index (As)
#pragma unroll
            for (int r = 0; r < 3; r++) {
                const uint32_t* arow = &As[(w * 3 + r) * 58 + 7 * g];
                uint32_t a[9];
#pragma unroll
                for (int i = 0; i < 9; i++) a[i] = arow[i];
                int k0 = (wl * 3 + r) * 3;          // local k index (Ws)
                uint2 w0 = *reinterpret_cast<const uint2*>(&Ws[(k0 + 0) * 64 + og * 2]);
                uint2 w1 = *reinterpret_cast<const uint2*>(&Ws[(k0 + 1) * 64 + og * 2]);
                uint2 w2 = *reinterpret_cast<const uint2*>(&Ws[(k0 + 2) * 64 + og * 2]);
#pragma unroll
                for (int p = 0; p < 7; p++) {
                    {
                        uint32_t x0 = a[p] ^ w0.x, x1 = a[p + 1] ^ w1.x, x2 = a[p + 2] ^ w2.x;
                        uint32_t t = acc[p][0];
                        t = __popc(maj3(x0, x1, x2)) * 65536u + t;   // IMAD (fma pipe)
                        t += __popc(xor3(x0, x1, x2));               // IADD (alu)
                        acc[p][0] = t;
                    }
                    {
                        uint32_t x0 = a[p] ^ w0.y, x1 = a[p + 1] ^ w1.y, x2 = a[p + 2] ^ w2.y;
                        uint32_t t = acc[p][1];
                        t = __popc(maj3(x0, x1, x2)) * 65536u + t;
                        t += __popc(xor3(x0, x1, x2));
                        acc[p][1] = t;
                    }
                }
            }
        }
    }
    __syncthreads();   // Ws reads done; region reusable

    // ---- epilogue ----
    int ocbase = ocq * 64 + og * 2;
    const float* Ag = (STAGE == 1) ? g_alpha1 : g_alpha2;
    const float* Cg = (STAGE == 1) ? g_c1 : g_c2;
    const int* NWg = (STAGE == 1) ? g_NW1 : g_NW2;
    float alpha[2], cc[2];
#pragma unroll
    for (int j = 0; j < 2; j++) { alpha[j] = __ldg(&Ag[ocbase + j]); cc[j] = __ldg(&Cg[ocbase + j]); }
    bool ybord = (y == 0) || (y == HH - 1);

#pragma unroll
    for (int p = 0; p < 7; p++) {
        int xx = 7 * g + p;
        bool bord = ybord || (xx == 0) || (xx == WW - 1);
        int nv = 9;
        int corr[2] = {0, 0};
        if (bord) {
#pragma unroll
            for (int t = 0; t < 9; t++) {
                int dy = t / 3 - 1, dx = t % 3 - 1;
                if ((unsigned)(y + dy) >= HH || (unsigned)(xx + dx) >= WW) {
                    nv--;
                    corr[0] += __ldg(&NWg[t * 256 + ocbase]);
                    corr[1] += __ldg(&NWg[t * 256 + ocbase + 1]);
                }
            }
        }
        if (STAGE == 1) {
            uint32_t sb = 0;
#pragma unroll
            for (int j = 0; j < 2; j++) {
                uint32_t av = acc[p][j];
                int ones = (int)(av & 0xFFFFu) + 2 * (int)(av >> 16);
                int dot = CTOT * nv - 2 * ones + 2 * corr[j];
                float val = (float)dot * alpha[j] + cc[j];
                val += Rs[(og * 2 + j) * 57 + xx];
                val = fminf(fmaxf(val, -1.f), 1.f);
                Vs[(og * 2 + j) * 57 + xx] = val;
                sb |= (val < 0.f ? 1u : 0u) << j;
            }
            stg[xx * 32 + og] = sb;
        } else {
#pragma unroll
            for (int j = 0; j < 2; j++) {
                uint32_t av = acc[p][j];
                int ones = (int)(av & 0xFFFFu) + 2 * (int)(av >> 16);
                int dot = CTOT * nv - 2 * ones + 2 * corr[j];
                Vs[(og * 2 + j) * 57 + xx] = (float)dot * alpha[j] + cc[j];
            }
        }
    }
    __syncthreads();

    // ---- coalesced writeout ----
    if (STAGE == 1) {
        if (ocq < 2) {
            for (int idx = tid; idx < 64 * WW; idx += 256) {
                int oc_l = idx / WW, px = idx % WW;
                g_Out1f[(((size_t)b * 128 + ocq * 64 + oc_l) * HH + y) * WW + px] =
                    Vs[oc_l * 57 + px];
            }
        }
        if (tid < 2 * WW) {
            int px = tid >> 1, wsel = tid & 1;
            uint32_t word = 0;
#pragma unroll
            for (int q = 0; q < 16; q++) {
                uint32_t v = stg[px * 32 + wsel * 16 + q];
                word |= (v & 1u) << (2 * q);
                word |= ((v >> 1) & 1u) << (2 * q + 1);
            }
            g_Sbits[((b * 16 + (ocq * 2 + wsel)) * HH + y) * WW + px] = word;
        }
    } else {
        for (int idx = tid; idx < 64 * WW; idx += 256) {
            int oc_l = idx / WW, px = idx % WW;
            int oc = ocq * 64 + oc_l;
            float v = Vs[oc_l * 57 + px];
            float res;
            if ((oc & 1) == 0)
                res = __ldg(&g_Out1f[(((size_t)b * 128 + (oc >> 1)) * HH + y) * WW + px]);
            else
                res = __ldg(&x[(((size_t)b * 512 + 256 + (oc >> 1)) * HH + y) * WW + px]) +
                      __ldg(&mb[oc >> 1]);
            v = fminf(fmaxf(v + res, -1.f), 1.f);
            out[(((size_t)b * 256 + oc) * HH + y) * WW + px] = v;
        }
    }
}

// ---------------- launch ----------------
extern "C" void kernel_launch(void* const* d_in, const int* in_sizes, int n_in,
                              void* d_out, int out_size) {
    const float* x      = (const float*)d_in[0];
    const float* w1     = (const float*)d_in[1];
    const float* w2     = (const float*)d_in[2];
    const float* gamma1 = (const float*)d_in[3];
    const float* beta1  = (const float*)d_in[4];
    const float* mean1  = (const float*)d_in[5];
    const float* var1   = (const float*)d_in[6];
    const float* gamma2 = (const float*)d_in[7];
    const float* beta2  = (const float*)d_in[8];
    const float* mean2  = (const float*)d_in[9];
    const float* var2   = (const float*)d_in[10];
    const float* mb     = (const float*)d_in[11];
    float* out = (float*)d_out;

    // stage1: Ws 72*64 + As 8*3*58 + Rs 64*57 = 38592 B -> 5 CTAs/SM
    // stage2: Ws 144*64 + As 16*3*58          = 48000 B -> 4 CTAs/SM
    const int smem1 = (72 * 64 + 8 * 3 * 58 + 64 * 57) * 4;
    const int smem2 = (144 * 64 + 16 * 3 * 58) * 4;
    cudaFuncSetAttribute(binconv<8, 1, 5, 1>,  cudaFuncAttributeMaxDynamicSharedMemorySize, smem1);
    cudaFuncSetAttribute(binconv<16, 2, 4, 1>, cudaFuncAttributeMaxDynamicSharedMemorySize, smem2);

    prep_w1<<<256, 256>>>(w1, gamma1, beta1, mean1, var1);
    prep_w2<<<256, 256>>>(w2, gamma2, beta2, mean2, var2);
    pack_input<<<(BATCH * 16 * NPIX + 255) / 256, 256>>>(x, mb);

    dim3 grid(4, HH, BATCH);
    binconv<8, 1, 5, 1><<<grid, 256, smem1>>>(x, mb, out);
    binconv<16, 2, 4, 1><<<grid, 256, smem2>>>(x, mb, out);
}